// round 17
// baseline (speedup 1.0000x reference)
#include <cuda_runtime.h>
#include <cstdint>

// ===========================================================================
// OctreeGnResBlock2: mma.sync tf32, BARRIER-FREE per-warp pipelines.
// Each warp owns 32 output rows (m32 x n64 tile), stages its own gathered
// A data into a warp-private smem buffer (depth-2 cp.async, warp-local
// wait_group + __syncwarp), and reads weights as pre-packed per-lane
// fragments via coalesced LDG.128 (L2-hot). No __syncthreads in any loop:
// warps slip freely past each other's gather tails.
//   kA : g_h = relu(GN_a(sum_k gather(x) @ Wa[k]))        27 K=32 stages
//   kB : out = relu(GN_b(sum_k gather(h) @ Wb[k]) + GN_s(x @ W1))
//        54 K=32 half-tap stages; shortcut via out-gmem two-phase epilogue
// CTA = 128 nodes / 128 thr (4 warps); smem = 4 warps x 2 x 4KB = 32KB.
// ===========================================================================

__device__ float  g_h  [800000ULL * 64];
__device__ float  g_xt [800000ULL * 32];
__device__ float4 g_WaF[27 * 2 * 8 * 32];   // [k][wn][chunk][lane]
__device__ float4 g_WbF[54 * 2 * 8 * 32];   // [halfstage][wn][chunk][lane]
__device__ float4 g_W1F[2 * 8 * 32];

__device__ __forceinline__ float totf32(float f) {
    uint32_t u;
    asm("cvt.rna.tf32.f32 %0, %1;" : "=r"(u) : "f"(f));
    return __uint_as_float(u);
}
__device__ __forceinline__ uint32_t s2u(const void* p) {
    uint32_t a;
    asm("{ .reg .u64 t; cvta.to.shared.u64 t, %1; cvt.u32.u64 %0, t; }"
        : "=r"(a) : "l"(p));
    return a;
}
__device__ __forceinline__ void cpa16(uint32_t d, const void* s) {
    asm volatile("cp.async.cg.shared.global [%0], [%1], 16;" :: "r"(d), "l"(s));
}
#define CPA_COMMIT() asm volatile("cp.async.commit_group;" ::: "memory")
#define CPA_WAIT(N)  asm volatile("cp.async.wait_group %0;" :: "n"(N) : "memory")

#define LDSM4(d0, d1, d2, d3, addr)                                          \
    asm volatile("ldmatrix.sync.aligned.m8n8.x4.shared.b16 {%0,%1,%2,%3}, [%4];" \
                 : "=r"(d0), "=r"(d1), "=r"(d2), "=r"(d3) : "r"(addr))

#define MMA(c, a, b0, b1)                                                    \
    asm volatile(                                                            \
        "mma.sync.aligned.m16n8k8.row.col.f32.tf32.tf32.f32 "                \
        "{%0,%1,%2,%3},{%4,%5,%6,%7},{%8,%9},{%0,%1,%2,%3};"                 \
        : "+f"((c)[0]), "+f"((c)[1]), "+f"((c)[2]), "+f"((c)[3])             \
        : "r"((a)[0]), "r"((a)[1]), "r"((a)[2]), "r"((a)[3]),                \
          "r"(b0), "r"(b1))

// one K=32 stage: warp-private A[32x32] @ Wfrag[64x32]^T (LDG) -> c[2][8][4]
__device__ __forceinline__ void mma_stageF(uint32_t aSt, const float4* wf,
                                           float c[2][8][4],
                                           uint32_t pA, uint32_t rxA) {
#pragma unroll
    for (uint32_t s2 = 0; s2 < 4; ++s2) {
        uint32_t a[2][4];
#pragma unroll
        for (int mi = 0; mi < 2; ++mi)
            LDSM4(a[mi][0], a[mi][1], a[mi][2], a[mi][3],
                  aSt + pA + mi * 2048u + (((2u * s2) ^ rxA) << 4));
        const float4 v00 = __ldg(wf + s2 * 64);
        const float4 v01 = __ldg(wf + s2 * 64 + 32);
        const float4 v10 = __ldg(wf + s2 * 64 + 256);
        const float4 v11 = __ldg(wf + s2 * 64 + 288);
        uint32_t b[8][2];
        b[0][0] = __float_as_uint(v00.x); b[0][1] = __float_as_uint(v00.y);
        b[1][0] = __float_as_uint(v00.z); b[1][1] = __float_as_uint(v00.w);
        b[2][0] = __float_as_uint(v01.x); b[2][1] = __float_as_uint(v01.y);
        b[3][0] = __float_as_uint(v01.z); b[3][1] = __float_as_uint(v01.w);
        b[4][0] = __float_as_uint(v10.x); b[4][1] = __float_as_uint(v10.y);
        b[5][0] = __float_as_uint(v10.z); b[5][1] = __float_as_uint(v10.w);
        b[6][0] = __float_as_uint(v11.x); b[6][1] = __float_as_uint(v11.y);
        b[7][0] = __float_as_uint(v11.z); b[7][1] = __float_as_uint(v11.w);
#pragma unroll
        for (int mi = 0; mi < 2; ++mi)
#pragma unroll
            for (int nt = 0; nt < 8; ++nt)
                MMA(c[mi][nt], a[mi], b[nt][0], b[nt][1]);
    }
}

// ---------------- prep ----------------
__global__ void k_prepX(const float* __restrict__ x, long long n32) {
    for (long long i = blockIdx.x * 256LL + threadIdx.x; i < n32;
         i += (long long)gridDim.x * 256)
        g_xt[i] = totf32(x[i]);
}
__global__ void k_prepF(const float* __restrict__ Wa,
                        const float* __restrict__ Wb,
                        const float* __restrict__ W1) {
    const int t = blockIdx.x * 256 + threadIdx.x;
    const int lane = t & 31, ch = (t >> 5) & 7, wn = (t >> 8) & 1;
    const int s2 = ch >> 1, j = ch & 1;
    const int r4 = lane & 3, q4 = lane >> 2;
    float v[4];
    if (t < 54 * 512) {                       // Wb half-stages
        const int s = t >> 9;
#pragma unroll
        for (int e2 = 0; e2 < 4; ++e2) {
            const int nn = j * 2 + (e2 >> 1), e = e2 & 1;
            const int cin = (s & 1) * 32 + 8 * s2 + 4 * e + r4;
            const int cout = wn * 32 + nn * 8 + q4;
            v[e2] = totf32(Wb[(s >> 1) * 4096 + cin * 64 + cout]);
        }
        g_WbF[t] = make_float4(v[0], v[1], v[2], v[3]);
    }
    if (t < 27 * 512) {                       // Wa taps
        const int k = t >> 9;
#pragma unroll
        for (int e2 = 0; e2 < 4; ++e2) {
            const int nn = j * 2 + (e2 >> 1), e = e2 & 1;
            const int cin = 8 * s2 + 4 * e + r4;
            const int cout = wn * 32 + nn * 8 + q4;
            v[e2] = totf32(Wa[k * 2048 + cin * 64 + cout]);
        }
        g_WaF[t] = make_float4(v[0], v[1], v[2], v[3]);
    }
    if (t < 512) {                            // W1
#pragma unroll
        for (int e2 = 0; e2 < 4; ++e2) {
            const int nn = j * 2 + (e2 >> 1), e = e2 & 1;
            const int cin = 8 * s2 + 4 * e + r4;
            const int cout = wn * 32 + nn * 8 + q4;
            v[e2] = totf32(W1[cin * 64 + cout]);
        }
        g_W1F[t] = make_float4(v[0], v[1], v[2], v[3]);
    }
}

static constexpr int SMB = 32768;   // 4 warps x 2 bufs x 4KB

// ---------------- kA: 27 K=32 taps -> g_h ----------------
__global__ void __launch_bounds__(128, 4) kA(
    const int* __restrict__ neigh, const float* __restrict__ gw,
    const float* __restrict__ gb, int n)
{
    extern __shared__ char smem[];
    const int tid = threadIdx.x, wid = tid >> 5, lid = tid & 31;
    const int tile = blockIdx.x;
    const int rows = min(128, n - tile * 128);
    const uint32_t aBase = s2u(smem) + (uint32_t)wid * 8192u;

    // lane l owns warp-local row l
    int myrow = 32 * wid + lid;
    if (myrow >= rows) myrow = 0;
    const int* nsrc = neigh + ((long long)tile * 128 + myrow) * 27;

    // staging constants: thread covers rows 4q + rq at 16B-chunk seg
    const int seg = lid & 7, rq = lid >> 3;
    const uint32_t base0 = aBase + 128u * rq + 16u * (uint32_t)(seg ^ rq);
    const uint32_t base1 = aBase + 128u * rq + 16u * (uint32_t)(seg ^ (rq + 4));

    // fragment constants
    const uint32_t r = lid & 7, h8 = (lid >> 3) & 1, kp = (uint32_t)lid >> 4;
    const uint32_t pA = (h8 * 8 + r) * 128u, rxA = kp ^ r;
    const int g = lid >> 2, t = lid & 3;

    float c[2][8][4];
#pragma unroll
    for (int mi = 0; mi < 2; ++mi)
#pragma unroll
        for (int nt = 0; nt < 8; ++nt)
#pragma unroll
            for (int j = 0; j < 4; ++j) c[mi][nt][j] = 0.f;

    auto stage = [&](int k, uint32_t so) {
        const int v = __ldg(nsrc + k);
#pragma unroll
        for (int q = 0; q < 8; ++q) {
            const long long idx = __shfl_sync(0xffffffffu, v, 4 * q + rq);
            cpa16(((q & 1) ? base1 : base0) + so + (uint32_t)q * 512u,
                  g_xt + idx * 32 + seg * 4);
        }
        CPA_COMMIT();
    };

    stage(0, 0u);
#pragma unroll 1
    for (int k = 0; k < 27; ++k) {
        const uint32_t so = (k & 1) ? 4096u : 0u;
        if (k + 1 < 27) { stage(k + 1, so ^ 4096u); CPA_WAIT(1); }
        else CPA_WAIT(0);
        __syncwarp();
        mma_stageF(aBase + so, g_WaF + k * 512 + lid, c, pA, rxA);
    }

    // epilogue: GN_a + ReLU, tf32-round -> g_h (warp-local)
#pragma unroll
    for (int mi = 0; mi < 2; ++mi)
#pragma unroll
        for (int h = 0; h < 2; ++h) {
            const int row = 32 * wid + mi * 16 + g + 8 * h;
#pragma unroll
            for (int nt = 0; nt < 8; ++nt) {
                const float v0 = c[mi][nt][2 * h], v1 = c[mi][nt][2 * h + 1];
                float s = v0 + v1;
                s += __shfl_xor_sync(0xffffffffu, s, 1);
                const float mu = s * 0.25f;
                const float d0 = v0 - mu, d1 = v1 - mu;
                float qv = d0 * d0 + d1 * d1;
                qv += __shfl_xor_sync(0xffffffffu, qv, 1);
                const float rs = rsqrtf(qv * 0.25f + 1e-5f);
                const int col = nt * 8 + t * 2;
                if (row < rows) {
                    float2 o;
                    o.x = totf32(fmaxf(fmaf(d0 * rs, __ldg(gw + col),
                                            __ldg(gb + col)), 0.f));
                    o.y = totf32(fmaxf(fmaf(d1 * rs, __ldg(gw + col + 1),
                                            __ldg(gb + col + 1)), 0.f));
                    *(float2*)(g_h + ((long long)tile * 128 + row) * 64 + col) = o;
                }
            }
        }
}

// ---------------- kB: 54 half-taps + shortcut via out round-trip ----------
__global__ void __launch_bounds__(128, 4) kB(
    const int* __restrict__ neigh,
    const float* __restrict__ gbw, const float* __restrict__ gbb,
    const float* __restrict__ gsw, const float* __restrict__ gsb,
    float* __restrict__ out, int n)
{
    extern __shared__ char smem[];
    const int tid = threadIdx.x, wid = tid >> 5, lid = tid & 31;
    const int tile = blockIdx.x;
    const int rows = min(128, n - tile * 128);
    const uint32_t aBase = s2u(smem) + (uint32_t)wid * 8192u;

    int myrow = 32 * wid + lid;
    if (myrow >= rows) myrow = 0;
    const int* nsrc = neigh + ((long long)tile * 128 + myrow) * 27;

    const int seg = lid & 7, rq = lid >> 3;
    const uint32_t base0 = aBase + 128u * rq + 16u * (uint32_t)(seg ^ rq);
    const uint32_t base1 = aBase + 128u * rq + 16u * (uint32_t)(seg ^ (rq + 4));

    const uint32_t r = lid & 7, h8 = (lid >> 3) & 1, kp = (uint32_t)lid >> 4;
    const uint32_t pA = (h8 * 8 + r) * 128u, rxA = kp ^ r;
    const int g = lid >> 2, t = lid & 3;

    float c[2][8][4];
#pragma unroll
    for (int mi = 0; mi < 2; ++mi)
#pragma unroll
        for (int nt = 0; nt < 8; ++nt)
#pragma unroll
            for (int j = 0; j < 4; ++j) c[mi][nt][j] = 0.f;

    auto stage = [&](int s, uint32_t so) {
        const int k = s >> 1, hf = (s & 1) * 32;
        const int v = __ldg(nsrc + k);
#pragma unroll
        for (int q = 0; q < 8; ++q) {
            const long long idx = __shfl_sync(0xffffffffu, v, 4 * q + rq);
            cpa16(((q & 1) ? base1 : base0) + so + (uint32_t)q * 512u,
                  g_h + idx * 64 + hf + seg * 4);
        }
        CPA_COMMIT();
    };

    stage(0, 0u);
#pragma unroll 1
    for (int s = 0; s < 54; ++s) {
        const uint32_t so = (s & 1) ? 4096u : 0u;
        if (s + 1 < 54) { stage(s + 1, so ^ 4096u); CPA_WAIT(1); }
        else CPA_WAIT(0);
        __syncwarp();
        mma_stageF(aBase + so, g_WbF + s * 512 + lid, c, pA, rxA);
    }

    // ---- shortcut gather into buf0 (warp-private; overlaps phase 1) ----
    {
#pragma unroll
        for (int q = 0; q < 8; ++q) {
            int row = 32 * wid + 4 * q + rq;
            const long long nd = (long long)tile * 128 + ((row < rows) ? row : 0);
            cpa16(((q & 1) ? base1 : base0) + (uint32_t)q * 512u,
                  g_xt + nd * 32 + seg * 4);
        }
        CPA_COMMIT();
    }

    // ---- phase 1: GN_b -> out (re-read in phase 2 by same thread) ----
#pragma unroll
    for (int mi = 0; mi < 2; ++mi)
#pragma unroll
        for (int h = 0; h < 2; ++h) {
            const int row = 32 * wid + mi * 16 + g + 8 * h;
#pragma unroll
            for (int nt = 0; nt < 8; ++nt) {
                const float v0 = c[mi][nt][2 * h], v1 = c[mi][nt][2 * h + 1];
                float s = v0 + v1;
                s += __shfl_xor_sync(0xffffffffu, s, 1);
                const float mub = s * 0.25f;
                const float d0 = v0 - mub, d1 = v1 - mub;
                float qv = d0 * d0 + d1 * d1;
                qv += __shfl_xor_sync(0xffffffffu, qv, 1);
                const float rb = rsqrtf(qv * 0.25f + 1e-5f);
                const int col = nt * 8 + t * 2;
                if (row < rows) {
                    float2 o;
                    o.x = fmaf(d0 * rb, __ldg(gbw + col), __ldg(gbb + col));
                    o.y = fmaf(d1 * rb, __ldg(gbw + col + 1), __ldg(gbb + col + 1));
                    *(float2*)(out + ((long long)tile * 128 + row) * 64 + col) = o;
                }
            }
        }

#pragma unroll
    for (int mi = 0; mi < 2; ++mi)
#pragma unroll
        for (int nt = 0; nt < 8; ++nt)
#pragma unroll
            for (int j = 0; j < 4; ++j) c[mi][nt][j] = 0.f;

    CPA_WAIT(0);
    __syncwarp();
    mma_stageF(aBase, g_W1F + lid, c, pA, rxA);

    // ---- phase 2: GN_s + add + ReLU -> out ----
#pragma unroll
    for (int mi = 0; mi < 2; ++mi)
#pragma unroll
        for (int h = 0; h < 2; ++h) {
            const int row = 32 * wid + mi * 16 + g + 8 * h;
#pragma unroll
            for (int nt = 0; nt < 8; ++nt) {
                const float v0 = c[mi][nt][2 * h], v1 = c[mi][nt][2 * h + 1];
                float s = v0 + v1;
                s += __shfl_xor_sync(0xffffffffu, s, 1);
                const float mus = s * 0.25f;
                const float e0 = v0 - mus, e1 = v1 - mus;
                float qv = e0 * e0 + e1 * e1;
                qv += __shfl_xor_sync(0xffffffffu, qv, 1);
                const float rss = rsqrtf(qv * 0.25f + 1e-5f);
                const int col = nt * 8 + t * 2;
                if (row < rows) {
                    const long long base = ((long long)tile * 128 + row) * 64 + col;
                    const float2 cv = *(float2*)(out + base);   // same thread wrote it
                    float2 o;
                    o.x = fmaxf(cv.x + fmaf(e0 * rss, __ldg(gsw + col),
                                            __ldg(gsb + col)), 0.f);
                    o.y = fmaxf(cv.y + fmaf(e1 * rss, __ldg(gsw + col + 1),
                                            __ldg(gsb + col + 1)), 0.f);
                    *(float2*)(out + base) = o;
                }
            }
        }
}

// ---------------------------------------------------------------------------
extern "C" void kernel_launch(void* const* d_in, const int* in_sizes, int n_in,
                              void* d_out, int out_size) {
    const float* data  = (const float*)d_in[0];
    const int*   neigh = (const int*)d_in[1];
    const float* Wa    = (const float*)d_in[2];
    const float* ga_w  = (const float*)d_in[3];
    const float* ga_b  = (const float*)d_in[4];
    const float* Wb    = (const float*)d_in[5];
    const float* gb_w  = (const float*)d_in[6];
    const float* gb_b  = (const float*)d_in[7];
    const float* W1    = (const float*)d_in[8];
    const float* gs_w  = (const float*)d_in[9];
    const float* gs_b  = (const float*)d_in[10];
    float* out = (float*)d_out;

    const int n = in_sizes[0] / 32;
    const int tiles = (n + 127) / 128;

    cudaFuncSetAttribute(kA, cudaFuncAttributeMaxDynamicSharedMemorySize, SMB);
    cudaFuncSetAttribute(kB, cudaFuncAttributeMaxDynamicSharedMemorySize, SMB);

    k_prepF<<<(54 * 512 + 255) / 256, 256>>>(Wa, Wb, W1);
    k_prepX<<<2048, 256>>>(data, (long long)n * 32);
    kA<<<tiles, 128, SMB>>>(neigh, ga_w, ga_b, n);
    kB<<<tiles, 128, SMB>>>(neigh, gb_w, gb_b, gs_w, gs_b, out, n);
}